// round 2
// baseline (speedup 1.0000x reference)
#include <cuda_runtime.h>
#include <math.h>

#define NPTS 2048
#define BATCH 16
#define KNN 20
#define NEG_SLOPE 0.2f
#define EPS 1e-5f

// ---------------- static device scratch (no runtime allocation) ----------------
__device__ float d_pdbuf[(size_t)NPTS * NPTS];              // 16 MB, per-batch pd (L2 resident)
__device__ int   d_idx[(size_t)BATCH * NPTS * KNN];         // knn indices
__device__ float d_xx[(size_t)BATCH * NPTS];                // squared norms
__device__ float d_xcat[(size_t)BATCH * 512 * NPTS];        // concatenated layer outputs
__device__ float d_g[(size_t)BATCH * 256 * NPTS];           // g = wA * x
__device__ float d_h[(size_t)BATCH * 256 * NPTS];           // h = (wB - wA) * x
__device__ float d_wdiff[256 * 128];                        // wB - wA
__device__ float d_y5[(size_t)BATCH * 512 * NPTS];          // final GEMM output
__device__ float d_stats[1024];                             // [mean(512), invstd(512)]

// ---------------- squared norms ----------------
__global__ __launch_bounds__(256)
void xx_kernel(const float* __restrict__ X, long xbs, int C, float* __restrict__ xx) {
    int n = blockIdx.x * 256 + threadIdx.x;
    int b = blockIdx.y;
    float s = 0.f;
    for (int c = 0; c < C; c++) {
        float v = X[(long)b * xbs + (long)c * NPTS + n];
        s += v * v;
    }
    xx[b * NPTS + n] = s;
}

// ---------------- generic batched GEMM: Out[b,o,n] = sum_c W[b*wbs + o*ws_o + c*ws_c] * X[b*xbs + c*N + n]
// mode==1: pairwise-distance epilogue: Out = 2*acc - xx[b,o] - xx[b,n]  (o plays role of i)
__global__ __launch_bounds__(256)
void gemm_kernel(const float* __restrict__ W, long wbs, int ws_o, int ws_c,
                 const float* __restrict__ X, long xbs,
                 float* __restrict__ Out, long obs,
                 int C, int mode, const float* __restrict__ xx, int bofs) {
    __shared__ float sW[8][64];
    __shared__ float sX[8][64];

    const int t  = threadIdx.x;
    const int tx = t & 15;          // n-direction (4 cols each)
    const int ty = t >> 4;          // o-direction (4 rows each)
    const int n0 = blockIdx.x * 64;
    const int o0 = blockIdx.y * 64;
    const int b  = blockIdx.z + bofs;

    float acc[16];
#pragma unroll
    for (int i = 0; i < 16; i++) acc[i] = 0.f;

    const bool wcontig = (ws_c == 1);

    for (int c0 = 0; c0 < C; c0 += 8) {
        // load X tile (coalesced along n)
#pragma unroll
        for (int l = 0; l < 2; l++) {
            int e = t + l * 256;
            int cc = e >> 6, nn = e & 63;
            int c = c0 + cc;
            sX[cc][nn] = (c < C) ? X[(long)b * xbs + (long)c * NPTS + (n0 + nn)] : 0.f;
        }
        // load W tile
        if (wcontig) {
#pragma unroll
            for (int l = 0; l < 2; l++) {
                int e = t + l * 256;
                int oo = e >> 3, cc = e & 7;
                int c = c0 + cc;
                sW[cc][oo] = (c < C) ? W[(long)b * wbs + (long)(o0 + oo) * ws_o + c] : 0.f;
            }
        } else {
#pragma unroll
            for (int l = 0; l < 2; l++) {
                int e = t + l * 256;
                int cc = e >> 6, oo = e & 63;
                int c = c0 + cc;
                sW[cc][oo] = (c < C) ? W[(long)b * wbs + (long)(o0 + oo) * ws_o + (long)c * ws_c] : 0.f;
            }
        }
        __syncthreads();
#pragma unroll
        for (int cc = 0; cc < 8; cc++) {
            float4 wv = *(const float4*)&sW[cc][ty * 4];
            float4 xv = *(const float4*)&sX[cc][tx * 4];
            acc[0]  += wv.x * xv.x; acc[1]  += wv.x * xv.y; acc[2]  += wv.x * xv.z; acc[3]  += wv.x * xv.w;
            acc[4]  += wv.y * xv.x; acc[5]  += wv.y * xv.y; acc[6]  += wv.y * xv.z; acc[7]  += wv.y * xv.w;
            acc[8]  += wv.z * xv.x; acc[9]  += wv.z * xv.y; acc[10] += wv.z * xv.z; acc[11] += wv.z * xv.w;
            acc[12] += wv.w * xv.x; acc[13] += wv.w * xv.y; acc[14] += wv.w * xv.z; acc[15] += wv.w * xv.w;
        }
        __syncthreads();
    }

    // epilogue
#pragma unroll
    for (int r = 0; r < 4; r++) {
        int o = o0 + ty * 4 + r;
        long ob = (long)b * obs + (long)o * NPTS + n0 + tx * 4;
        float4 v;
        v.x = acc[r * 4 + 0]; v.y = acc[r * 4 + 1]; v.z = acc[r * 4 + 2]; v.w = acc[r * 4 + 3];
        if (mode == 1) {
            float xi = xx[b * NPTS + o];
            int jb = n0 + tx * 4;
            v.x = 2.f * v.x - xi - xx[b * NPTS + jb + 0];
            v.y = 2.f * v.y - xi - xx[b * NPTS + jb + 1];
            v.z = 2.f * v.z - xi - xx[b * NPTS + jb + 2];
            v.w = 2.f * v.w - xi - xx[b * NPTS + jb + 3];
        }
        *(float4*)&Out[ob] = v;
    }
}

// ---------------- top-k (k=20) per row via iterative argmax in shared ----------------
__global__ __launch_bounds__(256)
void topk_kernel(int b) {
    __shared__ float v[NPTS];
    __shared__ float rv[256];
    __shared__ int   ri[256];
    const int i = blockIdx.x;
    const int tid = threadIdx.x;
    const size_t base = (size_t)i * NPTS;

#pragma unroll
    for (int r = 0; r < 8; r++) v[r * 256 + tid] = d_pdbuf[base + r * 256 + tid];
    __syncthreads();

    for (int sel = 0; sel < KNN; sel++) {
        float best = -3.4e38f;
        int bi = 0;
#pragma unroll
        for (int r = 0; r < 8; r++) {
            int j = r * 256 + tid;
            float val = v[j];
            if (val > best) { best = val; bi = j; }
        }
        rv[tid] = best; ri[tid] = bi;
        __syncthreads();
        for (int s = 128; s > 0; s >>= 1) {
            if (tid < s) {
                if (rv[tid + s] > rv[tid] ||
                    (rv[tid + s] == rv[tid] && ri[tid + s] < ri[tid])) {
                    rv[tid] = rv[tid + s]; ri[tid] = ri[tid + s];
                }
            }
            __syncthreads();
        }
        if (tid == 0) {
            d_idx[((size_t)b * NPTS + i) * KNN + sel] = ri[0];
            v[ri[0]] = -3.4e38f;
        }
        __syncthreads();
    }
}

// ---------------- wdiff = wB - wA ----------------
__global__ __launch_bounds__(256)
void wdiff_kernel(const float* __restrict__ w, float* __restrict__ wd, int C, int O) {
    int i = blockIdx.x * 256 + threadIdx.x;
    if (i < O * C) {
        int o = i / C, c = i % C;
        wd[i] = w[o * 2 * C + C + c] - w[o * 2 * C + c];
    }
}

// ---------------- edge aggregate: gather max/mean stats, instance norm, lrelu, k-max ----------------
__global__ __launch_bounds__(256)
void edge_kernel(const float* __restrict__ g, const float* __restrict__ h,
                 float* __restrict__ out, int O) {
    __shared__ float gsh[NPTS];
    __shared__ float rs[256];
    __shared__ float rs2[256];
    const int o = blockIdx.x;
    const int b = blockIdx.y;
    const int tid = threadIdx.x;

    const long rowbase = ((long)b * O + o) * NPTS;
    for (int j = tid; j < NPTS; j += 256) gsh[j] = g[rowbase + j];
    __syncthreads();

    float vmax[8], hn[8];
    float s = 0.f, s2 = 0.f;
#pragma unroll
    for (int r = 0; r < 8; r++) {
        int n = r * 256 + tid;
        float hv = h[rowbase + n];
        const int* ip = &d_idx[((size_t)b * NPTS + n) * KNN];
        float gm = -3.4e38f;
#pragma unroll
        for (int k = 0; k < KNN; k++) {
            float gv = gsh[ip[k]];
            float y = gv + hv;
            s += y; s2 += y * y;
            gm = fmaxf(gm, gv);
        }
        vmax[r] = gm;
        hn[r] = hv;
    }
    rs[tid] = s; rs2[tid] = s2;
    __syncthreads();
    for (int st = 128; st > 0; st >>= 1) {
        if (tid < st) { rs[tid] += rs[tid + st]; rs2[tid] += rs2[tid + st]; }
        __syncthreads();
    }
    const float cnt = (float)(NPTS * KNN);
    float mean = rs[0] / cnt;
    float var = rs2[0] / cnt - mean * mean;
    float inv = rsqrtf(var + EPS);

#pragma unroll
    for (int r = 0; r < 8; r++) {
        int n = r * 256 + tid;
        float z = (vmax[r] + hn[r] - mean) * inv;
        z = (z >= 0.f) ? z : NEG_SLOPE * z;
        out[(long)b * 512 * NPTS + (long)o * NPTS + n] = z;
    }
}

// ---------------- BN stats over (b, n) per channel ----------------
__global__ __launch_bounds__(256)
void bnstats_kernel(const float* __restrict__ y5, float* __restrict__ stats) {
    __shared__ float rs[256];
    __shared__ float rs2[256];
    const int o = blockIdx.x;
    const int tid = threadIdx.x;
    float s = 0.f, s2 = 0.f;
    for (int e = tid; e < BATCH * NPTS; e += 256) {
        int b = e >> 11;
        int n = e & (NPTS - 1);
        float v = y5[((long)b * 512 + o) * NPTS + n];
        s += v; s2 += v * v;
    }
    rs[tid] = s; rs2[tid] = s2;
    __syncthreads();
    for (int st = 128; st > 0; st >>= 1) {
        if (tid < st) { rs[tid] += rs[tid + st]; rs2[tid] += rs2[tid + st]; }
        __syncthreads();
    }
    if (tid == 0) {
        const float cnt = (float)(BATCH * NPTS);
        float mean = rs[0] / cnt;
        float var = rs2[0] / cnt - mean * mean;
        stats[o] = mean;
        stats[512 + o] = rsqrtf(var + EPS);
    }
}

// ---------------- final: normalize, affine, lrelu, max+mean over n ----------------
__global__ __launch_bounds__(256)
void final_kernel(const float* __restrict__ y5, const float* __restrict__ stats,
                  const float* __restrict__ gamma, const float* __restrict__ beta,
                  float* __restrict__ out) {
    __shared__ float rmx[256];
    __shared__ float rsm[256];
    const int o = blockIdx.x;
    const int b = blockIdx.y;
    const int tid = threadIdx.x;
    const float mean = stats[o], inv = stats[512 + o];
    const float ga = gamma[o], be = beta[o];

    float mx = -3.4e38f, sm = 0.f;
#pragma unroll
    for (int r = 0; r < 8; r++) {
        int n = r * 256 + tid;
        float y = y5[((long)b * 512 + o) * NPTS + n];
        float z = (y - mean) * inv * ga + be;
        z = (z >= 0.f) ? z : NEG_SLOPE * z;
        mx = fmaxf(mx, z);
        sm += z;
    }
    rmx[tid] = mx; rsm[tid] = sm;
    __syncthreads();
    for (int st = 128; st > 0; st >>= 1) {
        if (tid < st) {
            rmx[tid] = fmaxf(rmx[tid], rmx[tid + st]);
            rsm[tid] += rsm[tid + st];
        }
        __syncthreads();
    }
    if (tid == 0) {
        out[b * 1024 + o]       = rmx[0];
        out[b * 1024 + 512 + o] = rsm[0] / (float)NPTS;
    }
}

// ---------------- host driver ----------------
extern "C" void kernel_launch(void* const* d_in, const int* in_sizes, int n_in,
                              void* d_out, int out_size) {
    const float* x     = (const float*)d_in[0];
    const float* w1    = (const float*)d_in[1];
    const float* w2    = (const float*)d_in[2];
    const float* w3    = (const float*)d_in[3];
    const float* w4    = (const float*)d_in[4];
    const float* w5    = (const float*)d_in[5];
    const float* gamma = (const float*)d_in[6];
    const float* beta  = (const float*)d_in[7];
    float* out = (float*)d_out;

    float *pd, *xx, *xcat, *g, *h, *wdiff, *y5, *stats;
    int* idx;
    cudaGetSymbolAddress((void**)&pd,    d_pdbuf);
    cudaGetSymbolAddress((void**)&xx,    d_xx);
    cudaGetSymbolAddress((void**)&xcat,  d_xcat);
    cudaGetSymbolAddress((void**)&g,     d_g);
    cudaGetSymbolAddress((void**)&h,     d_h);
    cudaGetSymbolAddress((void**)&wdiff, d_wdiff);
    cudaGetSymbolAddress((void**)&y5,    d_y5);
    cudaGetSymbolAddress((void**)&stats, d_stats);
    cudaGetSymbolAddress((void**)&idx,   d_idx);
    (void)idx;

    struct Layer { const float* xin; long xbs; int C; const float* wt; int O; int coff; };
    Layer layers[4] = {
        { x,                    (long)3 * NPTS,   3,   w1, 64,  0   },
        { xcat,                 (long)512 * NPTS, 64,  w2, 64,  64  },
        { xcat + 64L * NPTS,    (long)512 * NPTS, 64,  w3, 128, 128 },
        { xcat + 128L * NPTS,   (long)512 * NPTS, 128, w4, 256, 256 },
    };

    for (int l = 0; l < 4; l++) {
        const Layer& L = layers[l];
        // squared norms
        xx_kernel<<<dim3(NPTS / 256, BATCH), 256>>>(L.xin, L.xbs, L.C, xx);
        // per-batch pairwise distance + top-k (pd buffer stays L2 resident)
        for (int b = 0; b < BATCH; b++) {
            gemm_kernel<<<dim3(NPTS / 64, NPTS / 64, 1), 256>>>(
                L.xin, L.xbs, /*ws_o=*/1, /*ws_c=*/NPTS,
                L.xin, L.xbs, pd, /*obs=*/0, L.C, /*mode=*/1, xx, /*bofs=*/b);
            topk_kernel<<<NPTS, 256>>>(b);
        }
        // weight diff
        wdiff_kernel<<<(L.O * L.C + 255) / 256, 256>>>(L.wt, wdiff, L.C, L.O);
        // g = wA * x ; h = (wB - wA) * x
        gemm_kernel<<<dim3(NPTS / 64, L.O / 64, BATCH), 256>>>(
            L.wt, 0, /*ws_o=*/2 * L.C, /*ws_c=*/1,
            L.xin, L.xbs, g, (long)L.O * NPTS, L.C, 0, nullptr, 0);
        gemm_kernel<<<dim3(NPTS / 64, L.O / 64, BATCH), 256>>>(
            wdiff, 0, /*ws_o=*/L.C, /*ws_c=*/1,
            L.xin, L.xbs, h, (long)L.O * NPTS, L.C, 0, nullptr, 0);
        // gather + instance norm + lrelu + k-max -> xcat slice
        edge_kernel<<<dim3(L.O, BATCH), 256>>>(g, h, xcat + (long)L.coff * NPTS, L.O);
    }

    // final linear over concatenated features
    gemm_kernel<<<dim3(NPTS / 64, 512 / 64, BATCH), 256>>>(
        w5, 0, /*ws_o=*/512, /*ws_c=*/1,
        xcat, (long)512 * NPTS, y5, (long)512 * NPTS, 512, 0, nullptr, 0);
    // batch norm stats + final pooling
    bnstats_kernel<<<512, 256>>>(y5, stats);
    final_kernel<<<dim3(512, BATCH), 256>>>(y5, stats, gamma, beta, out);
}

// round 4
// speedup vs baseline: 1.3038x; 1.3038x over previous
#include <cuda_runtime.h>
#include <math.h>

#define NPTS 2048
#define BATCH 16
#define KNN 20
#define NEG_SLOPE 0.2f
#define EPS 1e-5f

// ---------------- static device scratch ----------------
__device__ float d_pdbuf[(size_t)BATCH * NPTS * NPTS];   // 268 MB pairwise distances (all batches)
__device__ int   d_idx[(size_t)BATCH * NPTS * KNN];
__device__ float d_xx[(size_t)BATCH * NPTS];
__device__ float d_xcat[(size_t)BATCH * 512 * NPTS];
__device__ float d_gh[(size_t)BATCH * 512 * NPTS];       // stacked [g; h] per batch (2O<=512)
__device__ float d_wstack[512 * 128];                    // [wA ; wB-wA]
__device__ float d_y5[(size_t)BATCH * 512 * NPTS];
__device__ float d_stats[1024];

union U64F2 { unsigned long long u; float2 f; };

#define FMA_F32X2(d, a, b) \
    asm("fma.rn.f32x2 %0, %1, %2, %3;" : "=l"(d) : "l"(a), "l"(b), "l"(d))
#define PACK_SPLAT(d, a) \
    asm("mov.b64 %0, {%1, %1};" : "=l"(d) : "f"(a))

// ---------------- squared norms ----------------
__global__ __launch_bounds__(256)
void xx_kernel(const float* __restrict__ X, long xbs, int C, float* __restrict__ xx) {
    int n = blockIdx.x * 256 + threadIdx.x;
    int b = blockIdx.y;
    float s = 0.f;
    for (int c = 0; c < C; c++) {
        float v = X[(long)b * xbs + (long)c * NPTS + n];
        s += v * v;
    }
    xx[b * NPTS + n] = s;
}

// ---------------- 128x128x8 SGEMM, 8x8/thread, packed f32x2 FMA ----------------
// Out[b,o,n] = sum_c W[b*wbs + o*ws_o + c*ws_c] * X[b*xbs + c*NPTS + n]
// mode==1: pd epilogue Out = 2*acc - xx[o] - xx[n]
__global__ __launch_bounds__(256)
void gemm128(const float* __restrict__ W, long wbs, int ws_o, int ws_c,
             const float* __restrict__ X, long xbs,
             float* __restrict__ Out, long obs,
             int C, int mode, const float* __restrict__ xx) {
    __shared__ float sA[8][128];
    __shared__ float sB[8][128];

    const int t  = threadIdx.x;
    const int tx = t & 15;
    const int ty = t >> 4;
    const int n0 = blockIdx.x * 128;
    const int o0 = blockIdx.y * 128;
    const int b  = blockIdx.z;

    unsigned long long acc[8][4];
#pragma unroll
    for (int i = 0; i < 8; i++)
#pragma unroll
        for (int j = 0; j < 4; j++) acc[i][j] = 0ULL;

    const int lcc = t >> 5;
    const int lnn = (t & 31) * 4;

    for (int c0 = 0; c0 < C; c0 += 8) {
        int c = c0 + lcc;
        float4 xv = make_float4(0.f, 0.f, 0.f, 0.f);
        if (c < C) xv = *(const float4*)&X[(long)b * xbs + (long)c * NPTS + n0 + lnn];
        *(float4*)&sB[lcc][lnn] = xv;

        if (ws_o == 1) {
            // pd case: W has unit o-stride (coalesced along o)
            float4 wv = make_float4(0.f, 0.f, 0.f, 0.f);
            if (c < C) wv = *(const float4*)&W[(long)b * wbs + (long)c * ws_c + o0 + lnn];
            *(float4*)&sA[lcc][lnn] = wv;
        } else {
#pragma unroll
            for (int l = 0; l < 4; l++) {
                int idx = t * 4 + l;
                int oo = idx >> 3, cc = idx & 7;
                int cw = c0 + cc;
                sA[cc][oo] = (cw < C) ? W[(long)b * wbs + (long)(o0 + oo) * ws_o + cw] : 0.f;
            }
        }
        __syncthreads();

#pragma unroll
        for (int cc = 0; cc < 8; cc++) {
            float4 a0 = *(const float4*)&sA[cc][ty * 4];
            float4 a1 = *(const float4*)&sA[cc][ty * 4 + 64];
            ulonglong2 bp0 = *(const ulonglong2*)&sB[cc][tx * 4];
            ulonglong2 bp1 = *(const ulonglong2*)&sB[cc][tx * 4 + 64];
            unsigned long long bp[4] = { bp0.x, bp0.y, bp1.x, bp1.y };
            unsigned long long ap[8];
            PACK_SPLAT(ap[0], a0.x); PACK_SPLAT(ap[1], a0.y);
            PACK_SPLAT(ap[2], a0.z); PACK_SPLAT(ap[3], a0.w);
            PACK_SPLAT(ap[4], a1.x); PACK_SPLAT(ap[5], a1.y);
            PACK_SPLAT(ap[6], a1.z); PACK_SPLAT(ap[7], a1.w);
#pragma unroll
            for (int i = 0; i < 8; i++) {
                FMA_F32X2(acc[i][0], ap[i], bp[0]);
                FMA_F32X2(acc[i][1], ap[i], bp[1]);
                FMA_F32X2(acc[i][2], ap[i], bp[2]);
                FMA_F32X2(acc[i][3], ap[i], bp[3]);
            }
        }
        __syncthreads();
    }

    // epilogue
    float4 xj0 = make_float4(0.f, 0.f, 0.f, 0.f);
    float4 xj1 = make_float4(0.f, 0.f, 0.f, 0.f);
    if (mode == 1) {
        xj0 = *(const float4*)&xx[b * NPTS + n0 + tx * 4];
        xj1 = *(const float4*)&xx[b * NPTS + n0 + tx * 4 + 64];
    }
#pragma unroll
    for (int i = 0; i < 8; i++) {
        int o = o0 + ty * 4 + (i & 3) + ((i >= 4) ? 64 : 0);
        U64F2 u0, u1, u2, u3;
        u0.u = acc[i][0]; u1.u = acc[i][1]; u2.u = acc[i][2]; u3.u = acc[i][3];
        float4 v0 = make_float4(u0.f.x, u0.f.y, u1.f.x, u1.f.y);
        float4 v1 = make_float4(u2.f.x, u2.f.y, u3.f.x, u3.f.y);
        if (mode == 1) {
            float xi = xx[b * NPTS + o];
            v0.x = 2.f * v0.x - xi - xj0.x; v0.y = 2.f * v0.y - xi - xj0.y;
            v0.z = 2.f * v0.z - xi - xj0.z; v0.w = 2.f * v0.w - xi - xj0.w;
            v1.x = 2.f * v1.x - xi - xj1.x; v1.y = 2.f * v1.y - xi - xj1.y;
            v1.z = 2.f * v1.z - xi - xj1.z; v1.w = 2.f * v1.w - xi - xj1.w;
        }
        long ob = (long)b * obs + (long)o * NPTS + n0 + tx * 4;
        *(float4*)&Out[ob]      = v0;
        *(float4*)&Out[ob + 64] = v1;
    }
}

// ---------------- top-k (k=20), register-resident iterative argmax ----------------
__global__ __launch_bounds__(256)
void topk_all_kernel() {
    const int row = blockIdx.x;               // b*NPTS + i
    const int tid = threadIdx.x;
    const int lane = tid & 31, warp = tid >> 5;
    const float* __restrict__ src = d_pdbuf + (size_t)row * NPTS;

    float v[8];
#pragma unroll
    for (int r = 0; r < 8; r++) v[r] = src[r * 256 + tid];

    __shared__ float swv[8];
    __shared__ int   swi[8];
    __shared__ int   bci;

    for (int sel = 0; sel < KNN; sel++) {
        float best = v[0]; int br = 0;
#pragma unroll
        for (int r = 1; r < 8; r++)
            if (v[r] > best) { best = v[r]; br = r; }
        int bj = br * 256 + tid;
#pragma unroll
        for (int off = 16; off > 0; off >>= 1) {
            float ov = __shfl_down_sync(0xffffffffu, best, off);
            int   oj = __shfl_down_sync(0xffffffffu, bj, off);
            if (ov > best || (ov == best && oj < bj)) { best = ov; bj = oj; }
        }
        if (lane == 0) { swv[warp] = best; swi[warp] = bj; }
        __syncthreads();
        if (tid == 0) {
            float bb = swv[0]; int jj = swi[0];
#pragma unroll
            for (int w = 1; w < 8; w++)
                if (swv[w] > bb || (swv[w] == bb && swi[w] < jj)) { bb = swv[w]; jj = swi[w]; }
            bci = jj;
            d_idx[(size_t)row * KNN + sel] = jj;
        }
        __syncthreads();
        int jj = bci;
        if ((jj & 255) == tid) {
            int rr = jj >> 8;
#pragma unroll
            for (int r = 0; r < 8; r++)
                if (r == rr) v[r] = -3.4e38f;
        }
        __syncthreads();
    }
}

// ---------------- build stacked weights [wA ; wB - wA] ----------------
__global__ __launch_bounds__(256)
void wstack_kernel(const float* __restrict__ w, float* __restrict__ ws, int C, int O) {
    int i = blockIdx.x * 256 + threadIdx.x;
    if (i < 2 * O * C) {
        int o = i / C, c = i % C;
        if (o < O) ws[i] = w[o * 2 * C + c];
        else {
            int oo = o - O;
            ws[i] = w[oo * 2 * C + C + c] - w[oo * 2 * C + c];
        }
    }
}

// ---------------- edge aggregate: gather + instance norm + lrelu + k-max ----------------
__global__ __launch_bounds__(256)
void edge_kernel(const float* __restrict__ gh, float* __restrict__ out, int O) {
    __shared__ float gsh[NPTS];
    __shared__ float rs[256];
    __shared__ float rs2[256];
    const int o = blockIdx.x;
    const int b = blockIdx.y;
    const int tid = threadIdx.x;

    const long gbase = ((long)b * 2 * O + o) * NPTS;
    const long hbase = ((long)b * 2 * O + O + o) * NPTS;
    for (int j = tid; j < NPTS; j += 256) gsh[j] = gh[gbase + j];
    __syncthreads();

    float vmax[8], hn[8];
    float s = 0.f, s2 = 0.f;
#pragma unroll
    for (int r = 0; r < 8; r++) {
        int n = r * 256 + tid;
        float hv = gh[hbase + n];
        const int* ip = &d_idx[((size_t)b * NPTS + n) * KNN];
        float gm = -3.4e38f;
#pragma unroll
        for (int k = 0; k < KNN; k++) {
            float gv = gsh[ip[k]];
            float y = gv + hv;
            s += y; s2 += y * y;
            gm = fmaxf(gm, gv);
        }
        vmax[r] = gm;
        hn[r] = hv;
    }
    rs[tid] = s; rs2[tid] = s2;
    __syncthreads();
    for (int st = 128; st > 0; st >>= 1) {
        if (tid < st) { rs[tid] += rs[tid + st]; rs2[tid] += rs2[tid + st]; }
        __syncthreads();
    }
    const float cnt = (float)(NPTS * KNN);
    float mean = rs[0] / cnt;
    float var = rs2[0] / cnt - mean * mean;
    float inv = rsqrtf(var + EPS);

#pragma unroll
    for (int r = 0; r < 8; r++) {
        int n = r * 256 + tid;
        float z = (vmax[r] + hn[r] - mean) * inv;
        z = (z >= 0.f) ? z : NEG_SLOPE * z;
        out[(long)b * 512 * NPTS + (long)o * NPTS + n] = z;
    }
}

// ---------------- BN stats per channel ----------------
__global__ __launch_bounds__(256)
void bnstats_kernel(const float* __restrict__ y5, float* __restrict__ stats) {
    __shared__ float rs[256];
    __shared__ float rs2[256];
    const int o = blockIdx.x;
    const int tid = threadIdx.x;
    float s = 0.f, s2 = 0.f;
    for (int e = tid; e < BATCH * NPTS; e += 256) {
        int b = e >> 11;
        int n = e & (NPTS - 1);
        float v = y5[((long)b * 512 + o) * NPTS + n];
        s += v; s2 += v * v;
    }
    rs[tid] = s; rs2[tid] = s2;
    __syncthreads();
    for (int st = 128; st > 0; st >>= 1) {
        if (tid < st) { rs[tid] += rs[tid + st]; rs2[tid] += rs2[tid + st]; }
        __syncthreads();
    }
    if (tid == 0) {
        const float cnt = (float)(BATCH * NPTS);
        float mean = rs[0] / cnt;
        float var = rs2[0] / cnt - mean * mean;
        stats[o] = mean;
        stats[512 + o] = rsqrtf(var + EPS);
    }
}

// ---------------- final: affine BN + lrelu + max/mean pool ----------------
__global__ __launch_bounds__(256)
void final_kernel(const float* __restrict__ y5, const float* __restrict__ stats,
                  const float* __restrict__ gamma, const float* __restrict__ beta,
                  float* __restrict__ out) {
    __shared__ float rmx[256];
    __shared__ float rsm[256];
    const int o = blockIdx.x;
    const int b = blockIdx.y;
    const int tid = threadIdx.x;
    const float mean = stats[o], inv = stats[512 + o];
    const float ga = gamma[o], be = beta[o];

    float mx = -3.4e38f, sm = 0.f;
#pragma unroll
    for (int r = 0; r < 8; r++) {
        int n = r * 256 + tid;
        float y = y5[((long)b * 512 + o) * NPTS + n];
        float z = (y - mean) * inv * ga + be;
        z = (z >= 0.f) ? z : NEG_SLOPE * z;
        mx = fmaxf(mx, z);
        sm += z;
    }
    rmx[tid] = mx; rsm[tid] = sm;
    __syncthreads();
    for (int st = 128; st > 0; st >>= 1) {
        if (tid < st) {
            rmx[tid] = fmaxf(rmx[tid], rmx[tid + st]);
            rsm[tid] += rsm[tid + st];
        }
        __syncthreads();
    }
    if (tid == 0) {
        out[b * 1024 + o]       = rmx[0];
        out[b * 1024 + 512 + o] = rsm[0] / (float)NPTS;
    }
}

// ---------------- host driver ----------------
extern "C" void kernel_launch(void* const* d_in, const int* in_sizes, int n_in,
                              void* d_out, int out_size) {
    const float* x     = (const float*)d_in[0];
    const float* w1    = (const float*)d_in[1];
    const float* w2    = (const float*)d_in[2];
    const float* w3    = (const float*)d_in[3];
    const float* w4    = (const float*)d_in[4];
    const float* w5    = (const float*)d_in[5];
    const float* gamma = (const float*)d_in[6];
    const float* beta  = (const float*)d_in[7];
    float* out = (float*)d_out;

    float *pd, *xx, *xcat, *gh, *wstack, *y5, *stats;
    cudaGetSymbolAddress((void**)&pd,     d_pdbuf);
    cudaGetSymbolAddress((void**)&xx,     d_xx);
    cudaGetSymbolAddress((void**)&xcat,   d_xcat);
    cudaGetSymbolAddress((void**)&gh,     d_gh);
    cudaGetSymbolAddress((void**)&wstack, d_wstack);
    cudaGetSymbolAddress((void**)&y5,     d_y5);
    cudaGetSymbolAddress((void**)&stats,  d_stats);

    struct Layer { const float* xin; long xbs; int C; const float* wt; int O; int coff; };
    Layer layers[4] = {
        { x,                  (long)3 * NPTS,   3,   w1, 64,  0   },
        { xcat,               (long)512 * NPTS, 64,  w2, 64,  64  },
        { xcat + 64L * NPTS,  (long)512 * NPTS, 64,  w3, 128, 128 },
        { xcat + 128L * NPTS, (long)512 * NPTS, 128, w4, 256, 256 },
    };

    for (int l = 0; l < 4; l++) {
        const Layer& L = layers[l];
        xx_kernel<<<dim3(NPTS / 256, BATCH), 256>>>(L.xin, L.xbs, L.C, xx);
        // pairwise distances, all batches at once
        gemm128<<<dim3(NPTS / 128, NPTS / 128, BATCH), 256>>>(
            L.xin, L.xbs, /*ws_o=*/1, /*ws_c=*/NPTS,
            L.xin, L.xbs, pd, (long)NPTS * NPTS, L.C, /*mode=*/1, xx);
        // top-k for all rows of all batches
        topk_all_kernel<<<BATCH * NPTS, 256>>>();
        // stacked weights [wA ; wB-wA]
        wstack_kernel<<<(2 * L.O * L.C + 255) / 256, 256>>>(L.wt, wstack, L.C, L.O);
        // fused g/h GEMM (2O output rows)
        gemm128<<<dim3(NPTS / 128, 2 * L.O / 128, BATCH), 256>>>(
            wstack, 0, /*ws_o=*/L.C, /*ws_c=*/1,
            L.xin, L.xbs, gh, (long)2 * L.O * NPTS, L.C, 0, nullptr);
        // gather + instance norm + lrelu + k-max
        edge_kernel<<<dim3(L.O, BATCH), 256>>>(gh, xcat + (long)L.coff * NPTS, L.O);
    }

    // final linear over concatenated features
    gemm128<<<dim3(NPTS / 128, 512 / 128, BATCH), 256>>>(
        w5, 0, /*ws_o=*/512, /*ws_c=*/1,
        xcat, (long)512 * NPTS, y5, (long)512 * NPTS, 512, 0, nullptr);
    bnstats_kernel<<<512, 256>>>(y5, stats);
    final_kernel<<<dim3(512, BATCH), 256>>>(y5, stats, gamma, beta, out);
}